// round 4
// baseline (speedup 1.0000x reference)
#include <cuda_runtime.h>

#define B_     256
#define C_     3
#define H_     224
#define W_     224
#define HW_    (H_ * W_)        // 50176
#define HW4    (HW_ / 4)        // 12544 float4 per plane
#define NSLICE 16
#define SL4    (HW4 / NSLICE)   // 784 float4 per channel per slice (14 rows)
#define W4     (W_ / 4)         // 56 float4 per row
#define NT     256

// Cross-CTA scratch (no cudaMalloc allowed)
__device__ float g_part[B_ * NSLICE * 3];
__device__ int   g_cnt[B_];

__global__ void reset_kernel() { g_cnt[threadIdx.x] = 0; }

// One CTA per (image, slice). Stages its whole slice (3 channels) in smem,
// contributes partial sums, spins until all 16 slices of its image posted,
// then transforms from smem and streams out. Input read EXACTLY once.
__global__ __launch_bounds__(NT, 6) void fused_aug_kernel(
    const float* __restrict__ x,
    const float* __restrict__ brightness,
    const float* __restrict__ contrast_factor,
    const int*   __restrict__ flip_mask,
    const int*   __restrict__ gray_mask,
    const int*   __restrict__ contrast_apply,
    float*       __restrict__ out)
{
    __shared__ float4 st[3 * SL4];      // 37632 B
    __shared__ float  red[3][8];
    __shared__ float  sm_mean[3];

    const int b   = blockIdx.x >> 4;
    const int s   = blockIdx.x & (NSLICE - 1);
    const int tid = threadIdx.x;

    const float4* __restrict__ in4 =
        reinterpret_cast<const float4*>(x) + (size_t)b * 3 * HW4 + s * SL4;

    // ---------------- Phase 1: load slice -> smem, per-channel sums --------
    float acc[3];
    #pragma unroll
    for (int c = 0; c < 3; c++) {
        float a = 0.f;
        for (int i = tid; i < SL4; i += NT) {
            float4 v = __ldcs(&in4[c * HW4 + i]);
            st[c * SL4 + i] = v;
            a += (v.x + v.y) + (v.z + v.w);
        }
        acc[c] = a;
    }
    #pragma unroll
    for (int o = 16; o; o >>= 1) {
        acc[0] += __shfl_xor_sync(~0u, acc[0], o);
        acc[1] += __shfl_xor_sync(~0u, acc[1], o);
        acc[2] += __shfl_xor_sync(~0u, acc[2], o);
    }
    if ((tid & 31) == 0) {
        red[0][tid >> 5] = acc[0];
        red[1][tid >> 5] = acc[1];
        red[2][tid >> 5] = acc[2];
    }
    __syncthreads();

    // ---------------- Cross-CTA exchange (deterministic) -------------------
    if (tid == 0) {
        float p0 = 0.f, p1 = 0.f, p2 = 0.f;
        #pragma unroll
        for (int w = 0; w < 8; w++) { p0 += red[0][w]; p1 += red[1][w]; p2 += red[2][w]; }
        const int off = (b * NSLICE + s) * 3;
        g_part[off + 0] = p0;
        g_part[off + 1] = p1;
        g_part[off + 2] = p2;
        __threadfence();
        atomicAdd(&g_cnt[b], 1);
        volatile int* cnt = &g_cnt[b];
        while (*cnt < NSLICE) __nanosleep(64);
    }
    __syncthreads();

    if (tid < 3) {
        float m = 0.f;
        #pragma unroll
        for (int q = 0; q < NSLICE; q++)            // fixed order -> deterministic
            m += __ldcg(&g_part[(b * NSLICE + q) * 3 + tid]);
        sm_mean[tid] = m * (1.0f / (float)HW_);
    }
    __syncthreads();

    // ---------------- Per-batch coefficients -------------------------------
    const float br   = brightness[b];
    const bool  flip = flip_mask[b] != 0;
    const bool  gray = gray_mask[b] != 0;
    const float cf   = contrast_apply[b] ? contrast_factor[b] : 1.0f;

    const float m0 = sm_mean[0], m1 = sm_mean[1], m2 = sm_mean[2];
    const float gw0 = 0.2989f, gw1 = 0.587f, gw2 = 0.114f;
    const float gm  = gw0 * m0 + gw1 * m1 + gw2 * m2;

    const float mm0 = (gray ? gm : m0) * br;
    const float mm1 = (gray ? gm : m1) * br;
    const float mm2 = (gray ? gm : m2) * br;

    const float scale = br * cf;
    const float omcf  = 1.0f - cf;
    const float off0 = mm0 * omcf;
    const float off1 = mm1 * omcf;
    const float off2 = mm2 * omcf;

    float4* __restrict__ out4 =
        reinterpret_cast<float4*>(out) + (size_t)b * 3 * HW4 + s * SL4;

    // ---------------- Phase 2: transform from smem, stream out -------------
    for (int i = tid; i < SL4; i += NT) {
        int src = i;
        if (flip) {
            const int r  = i / W4;
            const int cc = i - r * W4;
            src = r * W4 + (W4 - 1 - cc);           // mirrored float4, same row
        }

        float4 v0 = st[0 * SL4 + src];
        float4 v1 = st[1 * SL4 + src];
        float4 v2 = st[2 * SL4 + src];

        if (flip) {
            float t;
            t = v0.x; v0.x = v0.w; v0.w = t;  t = v0.y; v0.y = v0.z; v0.z = t;
            t = v1.x; v1.x = v1.w; v1.w = t;  t = v1.y; v1.y = v1.z; v1.z = t;
            t = v2.x; v2.x = v2.w; v2.w = t;  t = v2.y; v2.y = v2.z; v2.z = t;
        }

        if (gray) {
            float4 g;
            g.x = gw0 * v0.x + gw1 * v1.x + gw2 * v2.x;
            g.y = gw0 * v0.y + gw1 * v1.y + gw2 * v2.y;
            g.z = gw0 * v0.z + gw1 * v1.z + gw2 * v2.z;
            g.w = gw0 * v0.w + gw1 * v1.w + gw2 * v2.w;
            v0 = g; v1 = g; v2 = g;
        }

        #define XFORM(v, off)                                                \
            v.x = fminf(fmaxf(fmaf(v.x, scale, off), -2.5f), 2.5f);          \
            v.y = fminf(fmaxf(fmaf(v.y, scale, off), -2.5f), 2.5f);          \
            v.z = fminf(fmaxf(fmaf(v.z, scale, off), -2.5f), 2.5f);          \
            v.w = fminf(fmaxf(fmaf(v.w, scale, off), -2.5f), 2.5f);
        XFORM(v0, off0)
        XFORM(v1, off1)
        XFORM(v2, off2)
        #undef XFORM

        __stcs(&out4[0 * HW4 + i], v0);
        __stcs(&out4[1 * HW4 + i], v1);
        __stcs(&out4[2 * HW4 + i], v2);
    }
}

extern "C" void kernel_launch(void* const* d_in, const int* in_sizes, int n_in,
                              void* d_out, int out_size) {
    const float* x   = (const float*)d_in[0];
    const float* br  = (const float*)d_in[1];
    const float* cfv = (const float*)d_in[2];
    const int*   fm  = (const int*)d_in[3];
    const int*   gm  = (const int*)d_in[4];
    const int*   ca  = (const int*)d_in[5];
    float* out = (float*)d_out;

    // Max L1/shared carveout so 6 CTAs/SM fit (6 x 37.6KB = 226KB)
    static bool configured = false;
    if (!configured) {
        cudaFuncSetAttribute(fused_aug_kernel,
                             cudaFuncAttributePreferredSharedMemoryCarveout, 100);
        configured = true;
    }

    reset_kernel<<<1, B_>>>();
    fused_aug_kernel<<<B_ * NSLICE, NT>>>(x, br, cfv, fm, gm, ca, out);
}

// round 5
// speedup vs baseline: 1.1509x; 1.1509x over previous
#include <cuda_runtime.h>

#define B_  256
#define C_  3
#define H_  224
#define W_  224
#define HW_ (H_ * W_)          // 50176
#define HW4 (HW_ / 4)          // 12544 float4 per plane
#define SLP 4                  // slices per plane (pass 1)
#define SLE (HW4 / SLP)        // 3136 float4 per slice

// Deterministic cross-kernel scratch: per-(plane,slice) partial sums
__device__ float g_part[B_ * C_ * SLP];

// ---------------------------------------------------------------------------
// Pass 1: per-slice sums. 3072 CTAs, no atomics. Reads populate L2 (evict-
// normal); the tail of the input stays L2-resident for pass 2.
// ---------------------------------------------------------------------------
__global__ __launch_bounds__(256) void plane_sum_kernel(const float* __restrict__ x) {
    const int bid = blockIdx.x;                          // plane*SLP + slice
    const float4* __restrict__ px =
        reinterpret_cast<const float4*>(x) + (size_t)(bid >> 2) * HW4 + (bid & 3) * SLE;
    const int tid = threadIdx.x;

    float s = 0.0f;
    #pragma unroll 4
    for (int i = tid; i < SLE; i += 256) {               // ~12.25 iters
        float4 v = px[i];
        s += (v.x + v.y) + (v.z + v.w);
    }
    #pragma unroll
    for (int o = 16; o; o >>= 1)
        s += __shfl_xor_sync(~0u, s, o);

    __shared__ float ws[8];
    if ((tid & 31) == 0) ws[tid >> 5] = s;
    __syncthreads();
    if (tid < 8) {
        s = ws[tid];
        #pragma unroll
        for (int o = 4; o; o >>= 1)
            s += __shfl_xor_sync(0xffu, s, o);
        if (tid == 0) g_part[bid] = s;
    }
}

// ---------------------------------------------------------------------------
// Pass 2: fused flip + gray + brightness + contrast + clip.
// Images processed in REVERSE order so pass 2 consumes the L2-resident tail
// that pass 1 just produced (LIFO matches LRU). Output stores are evict-first
// (__stcs) so the write stream doesn't flush the input out of L2.
// ---------------------------------------------------------------------------
__global__ __launch_bounds__(256) void transform_kernel(
    const float* __restrict__ x,
    const float* __restrict__ brightness,
    const float* __restrict__ contrast_factor,
    const int*   __restrict__ flip_mask,
    const int*   __restrict__ gray_mask,
    const int*   __restrict__ contrast_apply,
    float*       __restrict__ out)
{
    const int b = (B_ - 1) - blockIdx.y;                 // reverse image order
    const int p = blockIdx.x * 256 + threadIdx.x;        // float4 idx in plane
    if (p >= HW4) return;

    // Per-batch scalars (broadcast, L1/L2-hot)
    const float br   = brightness[b];
    const bool  flip = flip_mask[b] != 0;
    const bool  gray = gray_mask[b] != 0;
    const float cf   = contrast_apply[b] ? contrast_factor[b] : 1.0f;

    // Deterministic fixed-order reduction of pass-1 partials
    float m0 = 0.f, m1 = 0.f, m2 = 0.f;
    #pragma unroll
    for (int q = 0; q < SLP; q++) {
        m0 += g_part[(b * 3 + 0) * SLP + q];
        m1 += g_part[(b * 3 + 1) * SLP + q];
        m2 += g_part[(b * 3 + 2) * SLP + q];
    }
    const float inv_hw = 1.0f / (float)HW_;
    m0 *= inv_hw; m1 *= inv_hw; m2 *= inv_hw;

    const float gw0 = 0.2989f, gw1 = 0.587f, gw2 = 0.114f;
    const float gm  = gw0 * m0 + gw1 * m1 + gw2 * m2;

    const float mm0 = (gray ? gm : m0) * br;
    const float mm1 = (gray ? gm : m1) * br;
    const float mm2 = (gray ? gm : m2) * br;

    const float scale = br * cf;
    const float omcf  = 1.0f - cf;
    const float off0 = mm0 * omcf;
    const float off1 = mm1 * omcf;
    const float off2 = mm2 * omcf;

    // Source location (horizontal flip = mirrored float4, lanes reversed)
    const int pix  = p * 4;
    const int h    = pix / W_;
    const int w    = pix - h * W_;
    const int sp4  = flip ? ((h * W_ + (W_ - 4 - w)) >> 2) : p;

    const float4* __restrict__ in4 =
        reinterpret_cast<const float4*>(x) + (size_t)b * 3 * HW4;
    float4 v0 = in4[0 * HW4 + sp4];
    float4 v1 = in4[1 * HW4 + sp4];
    float4 v2 = in4[2 * HW4 + sp4];

    if (flip) {
        float t;
        t = v0.x; v0.x = v0.w; v0.w = t;  t = v0.y; v0.y = v0.z; v0.z = t;
        t = v1.x; v1.x = v1.w; v1.w = t;  t = v1.y; v1.y = v1.z; v1.z = t;
        t = v2.x; v2.x = v2.w; v2.w = t;  t = v2.y; v2.y = v2.z; v2.z = t;
    }

    if (gray) {
        float4 g;
        g.x = gw0 * v0.x + gw1 * v1.x + gw2 * v2.x;
        g.y = gw0 * v0.y + gw1 * v1.y + gw2 * v2.y;
        g.z = gw0 * v0.z + gw1 * v1.z + gw2 * v2.z;
        g.w = gw0 * v0.w + gw1 * v1.w + gw2 * v2.w;
        v0 = g; v1 = g; v2 = g;
    }

    #define XFORM(v, off)                                                    \
        v.x = fminf(fmaxf(fmaf(v.x, scale, off), -2.5f), 2.5f);             \
        v.y = fminf(fmaxf(fmaf(v.y, scale, off), -2.5f), 2.5f);             \
        v.z = fminf(fmaxf(fmaf(v.z, scale, off), -2.5f), 2.5f);             \
        v.w = fminf(fmaxf(fmaf(v.w, scale, off), -2.5f), 2.5f);
    XFORM(v0, off0)
    XFORM(v1, off1)
    XFORM(v2, off2)
    #undef XFORM

    float4* __restrict__ out4 =
        reinterpret_cast<float4*>(out) + (size_t)b * 3 * HW4;
    __stcs(&out4[0 * HW4 + p], v0);
    __stcs(&out4[1 * HW4 + p], v1);
    __stcs(&out4[2 * HW4 + p], v2);
}

extern "C" void kernel_launch(void* const* d_in, const int* in_sizes, int n_in,
                              void* d_out, int out_size) {
    const float* x   = (const float*)d_in[0];
    const float* br  = (const float*)d_in[1];
    const float* cfv = (const float*)d_in[2];
    const int*   fm  = (const int*)d_in[3];
    const int*   gm  = (const int*)d_in[4];
    const int*   ca  = (const int*)d_in[5];
    float* out = (float*)d_out;

    plane_sum_kernel<<<B_ * C_ * SLP, 256>>>(x);
    dim3 grid((HW4 + 255) / 256, B_);                    // (49, 256)
    transform_kernel<<<grid, 256>>>(x, br, cfv, fm, gm, ca, out);
}